// round 12
// baseline (speedup 1.0000x reference)
#include <cuda_runtime.h>
#include <math.h>

#define D_  64
#define H_  512
#define W_  512
#define NB  2
#define HW  (H_*W_)                 // 262144
#define NT  (NB*D_*H_*W_)           // 33554432
#define PAD 5
#define KS  11
#define CH  64                      // H rows per block in fused WH kernel
#define WP  (W_ + 2*PAD)            // padded smem row: 522
#define NROWS (CH + 2*PAD)          // 74 input rows per block
#define SMEM_WH (2 * KS * 2 * WP * 4)   // 2 bufs x 11 rows x 2 fields x WP floats

typedef unsigned long long u64;

// Scratch after W+H blur: float4 plane (x,y,xx,yy) + scalar plane (xy).
__device__ float4 g_s4[(size_t)NT];
__device__ float  g_s1[(size_t)NT];
__device__ double g_acc;

struct GW { float g[KS]; };

// ---- packed f32x2 helpers ---------------------------------------------------
__device__ __forceinline__ u64 pk2(float lo, float hi) {
    u64 r; asm("mov.b64 %0, {%1, %2};" : "=l"(r) : "f"(lo), "f"(hi)); return r;
}
__device__ __forceinline__ void upk2(u64 v, float& lo, float& hi) {
    asm("mov.b64 {%0, %1}, %2;" : "=f"(lo), "=f"(hi) : "l"(v));
}
__device__ __forceinline__ u64 fma2(u64 a, u64 b, u64 c) {
    u64 d; asm("fma.rn.f32x2 %0, %1, %2, %3;" : "=l"(d) : "l"(a), "l"(b), "l"(c));
    return d;
}
__device__ __forceinline__ u64 mul2(u64 a, u64 b) {
    u64 d; asm("mul.rn.f32x2 %0, %1, %2;" : "=l"(d) : "l"(a), "l"(b));
    return d;
}

// Gaussian is symmetric: g[t] == g[10-t]; 6 unique packed weights.
#define GSYM(t) ((t) <= 5 ? (t) : 10 - (t))

// ---------------------------------------------------------------------------
__global__ void k_zero_acc() { g_acc = 0.0; }

// ---------------------------------------------------------------------------
// Fused W+H blur, group-staged: one block = one 64-row strip of one (n,d)
// slice, 512 threads (one per w). Rows are processed in 7 groups of 11: stage
// all 11 rows of a group into smem (22 back-to-back LDGs -> high MLP), ONE
// __syncthreads, then compute 11 rows uninterrupted. Two group buffers make
// one sync per group sufficient (group g+2's writes happen after sync(g+1),
// which post-dates all reads of group g).
//
// Slot protocol: output h lives in slot (h-h0) mod 11. At row j, the k=10
// term is the FIRST contribution of new output h0+j (weight g[0], slot u=j%11)
// and is an ASSIGNMENT (kills the stale tenant).
__global__ void __launch_bounds__(512, 1) k_wh(const float* __restrict__ x,
                                               const float* __restrict__ y,
                                               GW gw) {
    extern __shared__ float sm[];   // [2][11][2][WP]
    int b  = blockIdx.x;
    int hc = b & 7;                 // H_/CH = 8 strips
    int nd = b >> 3;                // n*D_ + d
    int h0 = hc << 6;               // * CH
    size_t slice = (size_t)nd * HW;
    int w = threadIdx.x;

    const float* xsl = x + slice;
    const float* ysl = y + slice;

    u64 gg6[6];
#pragma unroll
    for (int t = 0; t < 6; t++) gg6[t] = pk2(gw.g[t], gw.g[t]);

    u64 acc01[11], acc23[11];
    float acc4[11];
#pragma unroll
    for (int s = 0; s < 11; s++) { acc01[s] = 0; acc23[s] = 0; acc4[s] = 0.f; }

    bool lpad = (w < PAD);
    bool rpad = (w >= W_ - PAD);

    // 7 groups of 11 rows; j = g*11 + u, valid while j < NROWS (74).
#pragma unroll 1
    for (int g = 0; g < 7; g++) {
        int gb = g & 1;
        float* base = sm + (size_t)gb * (KS * 2 * WP);

        // ---- stage 11 rows (all LDGs issued close together) ----
#pragma unroll
        for (int u = 0; u < 11; u++) {
            int j = g * 11 + u;
            if (j < NROWS) {
                int r  = h0 - PAD + j;
                int rr = r < 0 ? 0 : (r > H_ - 1 ? H_ - 1 : r);
                const float* xr = xsl + (size_t)rr * W_;
                const float* yr = ysl + (size_t)rr * W_;
                float* xrow = base + u * (2 * WP);
                float* yrow = xrow + WP;
                float xv = xr[w], yv = yr[w];
                xrow[PAD + w] = xv;
                yrow[PAD + w] = yv;
                if (lpad) { xrow[w] = xr[0];  yrow[w] = yr[0]; }
                if (rpad) { xrow[w + 2*PAD] = xr[W_ - 1];
                            yrow[w + 2*PAD] = yr[W_ - 1]; }
            }
        }
        __syncthreads();

        // ---- compute 11 rows ----
#pragma unroll
        for (int u = 0; u < 11; u++) {
            int j = g * 11 + u;
            if (j < NROWS) {
                const float* xrow = base + u * (2 * WP);
                const float* yrow = xrow + WP;

                // W-blur of the 5 product fields (packed: (sx,sy),(sxx,syy)).
                u64 s01 = 0, s23 = 0;
                float s4 = 0.f;
#pragma unroll
                for (int t = 0; t < KS; t++) {
                    float xv = xrow[w + t];
                    float yv = yrow[w + t];
                    u64 p  = pk2(xv, yv);
                    u64 g2 = gg6[GSYM(t)];
                    s01 = fma2(g2, p, s01);
                    u64 pp = mul2(p, p);
                    s23 = fma2(g2, pp, s23);
                    s4  = fmaf(gw.g[GSYM(t)] * xv, yv, s4);
                }

                // Row contributes to outputs h = r-5+k with weight g[10-k];
                // slot(h) = (u + k + 1) mod 11 (static).
#pragma unroll
                for (int k = 0; k < 10; k++) {
                    int s = (u + k + 1) % 11;
                    u64 g2 = gg6[GSYM(10 - k)];
                    acc01[s] = fma2(g2, s01, acc01[s]);
                    acc23[s] = fma2(g2, s23, acc23[s]);
                    acc4[s]  = fmaf(gw.g[GSYM(10 - k)], s4, acc4[s]);
                }
                // k = 10: first contribution of output h0+j -> ASSIGN slot u.
                acc01[u] = mul2(gg6[0], s01);
                acc23[u] = mul2(gg6[0], s23);
                acc4[u]  = gw.g[0] * s4;

                // Output h = h0+j-10 completes at this row (slot (u+1)%11).
                if (j >= 10) {
                    int h = h0 + j - 10;
                    int s = (u + 1) % 11;
                    size_t o = slice + (size_t)h * W_ + w;
                    float a0, a1, a2, a3;
                    upk2(acc01[s], a0, a1);
                    upk2(acc23[s], a2, a3);
                    __stcs(&g_s4[o], make_float4(a0, a1, a2, a3));
                    __stcs(&g_s1[o], acc4[s]);
                }
            }
        }
    }
}

// ---------------------------------------------------------------------------
// D-pass: rotating register window (no shifts — slots static via unroll-by-11),
// fused SSIM map + mean reduction. 2 wide loads per iteration (.128 + .32).
__global__ void __launch_bounds__(256) k_pass_d(GW gw) {
    int col = blockIdx.x * blockDim.x + threadIdx.x;   // 0 .. NB*HW-1
    int n   = col >> 18;            // / HW
    int hw  = col & (HW - 1);
    size_t base = (size_t)n * D_ * HW + hw;

    const float c1 = 0.01f * 0.01f;
    const float c2 = 0.03f * 0.03f;

    // At iteration d, window element k (depth d-5+k) lives in slot (d+k)%11.
    float4 win4[KS];
    float  win1[KS];
#pragma unroll
    for (int k = 0; k < KS; k++) {
        int dj = k - PAD;
        dj = dj < 0 ? 0 : dj;
        size_t off = base + (size_t)dj * HW;
        win4[k] = __ldcs(&g_s4[off]);
        win1[k] = __ldcs(&g_s1[off]);
    }

    float lsum = 0.f;
#pragma unroll 1
    for (int dbase = 0; dbase < 66; dbase += 11) {
#pragma unroll
        for (int u = 0; u < 11; u++) {
            int d = dbase + u;
            float s0 = 0.f, s1 = 0.f, s2 = 0.f, s3 = 0.f, s4 = 0.f;
#pragma unroll
            for (int k = 0; k < KS; k++) {
                float g = gw.g[GSYM(k)];
                int s = (u + k) % 11;          // static
                s0 += g * win4[s].x;
                s1 += g * win4[s].y;
                s2 += g * win4[s].z;
                s3 += g * win4[s].w;
                s4 += g * win1[s];
            }
            float mu_x = s0, mu_y = s1;
            float mu_x2 = mu_x * mu_x;
            float mu_y2 = mu_y * mu_y;
            float mu_xy = mu_x * mu_y;
            float sig_x  = fmaxf(s2 - mu_x2, 0.f);
            float sig_y  = fmaxf(s3 - mu_y2, 0.f);
            float sig_xy = s4 - mu_xy;
            float num = (2.f * mu_xy + c1) * (2.f * sig_xy + c2);
            float den = (mu_x2 + mu_y2 + c1) * (sig_x + sig_y + c2);
            if (d < D_) lsum += num / den;

            // Replace oldest (depth d-5, slot d%11 == u) with depth d+6.
            int dn = d + PAD + 1;
            dn = dn > D_ - 1 ? D_ - 1 : dn;
            size_t off = base + (size_t)dn * HW;
            win4[u] = __ldcs(&g_s4[off]);
            win1[u] = __ldcs(&g_s1[off]);
        }
    }

    // block reduction
    unsigned lane = threadIdx.x & 31;
    unsigned wid  = threadIdx.x >> 5;
#pragma unroll
    for (int o = 16; o > 0; o >>= 1)
        lsum += __shfl_xor_sync(0xffffffffu, lsum, o);
    __shared__ float ws[8];
    if (lane == 0) ws[wid] = lsum;
    __syncthreads();
    if (wid == 0) {
        float v = lane < (blockDim.x >> 5) ? ws[lane] : 0.f;
#pragma unroll
        for (int o = 4; o > 0; o >>= 1)
            v += __shfl_xor_sync(0xffffffffu, v, o);
        if (lane == 0) atomicAdd(&g_acc, (double)v);
    }
}

// ---------------------------------------------------------------------------
__global__ void k_finalize(float* __restrict__ out, int n) {
    double mean = g_acc / (double)NT;
    for (int i = threadIdx.x; i < n; i += blockDim.x)
        out[i] = (float)mean;
}

// ---------------------------------------------------------------------------
extern "C" void kernel_launch(void* const* d_in, const int* in_sizes, int n_in,
                              void* d_out, int out_size) {
    const float* x = (const float*)d_in[0];
    const float* y = (const float*)d_in[1];
    float* out = (float*)d_out;

    GW gw;
    {
        double g[KS], s = 0.0;
        for (int i = 0; i < KS; i++) {
            double c = (double)(i - KS / 2);
            g[i] = exp(-(c * c) / (2.0 * 1.5 * 1.5));
            s += g[i];
        }
        for (int i = 0; i < KS; i++) gw.g[i] = (float)(g[i] / s);
    }

    // Host-side attribute set (no allocation; legal under graph capture).
    cudaFuncSetAttribute(k_wh, cudaFuncAttributeMaxDynamicSharedMemorySize,
                         SMEM_WH);

    k_zero_acc<<<1, 1>>>();
    k_wh<<<NB * D_ * (H_ / CH), 512, SMEM_WH>>>(x, y, gw);
    k_pass_d<<<(NB * HW) / 256, 256>>>(gw);
    k_finalize<<<1, 32>>>(out, out_size);
}

// round 13
// speedup vs baseline: 1.1968x; 1.1968x over previous
#include <cuda_runtime.h>
#include <math.h>

#define D_  64
#define H_  512
#define W_  512
#define NB  2
#define HW  (H_*W_)                 // 262144
#define NT  (NB*D_*H_*W_)           // 33554432
#define PAD 5
#define KS  11
#define CH  64                      // H rows per block strip
#define BW  256                     // W columns per block (half row)
#define BWP (BW + 2*PAD)            // padded smem row: 266

typedef unsigned long long u64;

// Scratch after W+H blur: float4 plane (x,y,xx,yy) + scalar plane (xy).
__device__ float4 g_s4[(size_t)NT];
__device__ float  g_s1[(size_t)NT];
__device__ double g_acc;

struct GW { float g[KS]; };

// ---- packed f32x2 helpers ---------------------------------------------------
__device__ __forceinline__ u64 pk2(float lo, float hi) {
    u64 r; asm("mov.b64 %0, {%1, %2};" : "=l"(r) : "f"(lo), "f"(hi)); return r;
}
__device__ __forceinline__ void upk2(u64 v, float& lo, float& hi) {
    asm("mov.b64 {%0, %1}, %2;" : "=f"(lo), "=f"(hi) : "l"(v));
}
__device__ __forceinline__ u64 fma2(u64 a, u64 b, u64 c) {
    u64 d; asm("fma.rn.f32x2 %0, %1, %2, %3;" : "=l"(d) : "l"(a), "l"(b), "l"(c));
    return d;
}
__device__ __forceinline__ u64 mul2(u64 a, u64 b) {
    u64 d; asm("mul.rn.f32x2 %0, %1, %2;" : "=l"(d) : "l"(a), "l"(b));
    return d;
}

// Gaussian is symmetric: g[t] == g[10-t]; 6 unique packed weights.
#define GSYM(t) ((t) <= 5 ? (t) : 10 - (t))

// ---------------------------------------------------------------------------
__global__ void k_zero_acc() { g_acc = 0.0; }
__global__ void k_noop1() {}
__global__ void k_noop2() {}

// ---------------------------------------------------------------------------
// Fused W+H blur, half-row blocks: one block = 256 W-columns x 64 H-rows of
// one (n,d) slice, one thread per column, 2 independent blocks/SM (split
// barriers: when one block drains at __syncthreads, the other keeps issuing).
// Per input row: prefetch next row (+ halo/pad values for edge threads), stage
// padded row segment in smem (double buffered, clamp-free W-blur), W-blur the
// 5 product fields with packed f32x2 math, scatter-accumulate into 11 pending
// H outputs in packed registers (unroll-by-11 => static slots).
//
// Slot protocol: output h lives in slot (h-h0) mod 11. At row j, the k=10
// term is the FIRST contribution of new output h0+j (weight g[0], slot u=j%11)
// and is an ASSIGNMENT (kills the stale tenant).
__global__ void __launch_bounds__(256, 2) k_wh(const float* __restrict__ x,
                                               const float* __restrict__ y,
                                               GW gw) {
    __shared__ float xs[2][BWP], ys[2][BWP];
    int b  = blockIdx.x;
    int whalf = b & 1;              // which half of the row
    int hc = (b >> 1) & 7;          // H_/CH = 8 strips
    int nd = b >> 4;                // n*D_ + d
    int h0 = hc << 6;               // * CH
    int w0 = whalf << 8;            // * BW
    size_t slice = (size_t)nd * HW;
    int t = threadIdx.x;
    int wg = w0 + t;                // this thread's global column

    const float* xsl = x + slice;
    const float* ysl = y + slice;

    u64 gg6[6];
#pragma unroll
    for (int i = 0; i < 6; i++) gg6[i] = pk2(gw.g[i], gw.g[i]);

    u64 acc01[11], acc23[11];
    float acc4[11];
#pragma unroll
    for (int s = 0; s < 11; s++) { acc01[s] = 0; acc23[s] = 0; acc4[s] = 0.f; }

    bool lpad = (t < PAD);
    bool rpad = (t >= BW - PAD);
    // Halo global columns (clamped replicate at true volume edges).
    int glc = w0 - PAD + t;  glc = glc < 0 ? 0 : glc;            // for t<5
    int grc = wg + PAD;      grc = grc > W_ - 1 ? W_ - 1 : grc;  // for t>=251

    // Prefetch row j=0 (+ halo values for edge threads).
    float px, py, plx = 0.f, ply = 0.f, prx = 0.f, pry = 0.f;
    {
        int r = h0 - PAD;
        int rr = r < 0 ? 0 : r;
        const float* xr = xsl + (size_t)rr * W_;
        const float* yr = ysl + (size_t)rr * W_;
        px = xr[wg];  py = yr[wg];
        if (lpad) { plx = xr[glc]; ply = yr[glc]; }
        if (rpad) { prx = xr[grc]; pry = yr[grc]; }
    }

    // Input rows r = h0-5 .. h0+CH+4  (j = 0..73), padded to 77 for unroll.
#pragma unroll 1
    for (int jb = 0; jb < 77; jb += 11) {
#pragma unroll
        for (int u = 0; u < 11; u++) {
            int j = jb + u;
            if (j < CH + 10) {
                int buf = j & 1;
                xs[buf][PAD + t] = px;
                ys[buf][PAD + t] = py;
                if (lpad) { xs[buf][t] = plx; ys[buf][t] = ply; }
                if (rpad) { xs[buf][t + 2*PAD] = prx; ys[buf][t + 2*PAD] = pry; }
                __syncthreads();

                // Prefetch row j+1 (overlaps with compute below).
                {
                    int r = h0 - PAD + j + 1;
                    int rr = r < 0 ? 0 : (r > H_ - 1 ? H_ - 1 : r);
                    const float* xr = xsl + (size_t)rr * W_;
                    const float* yr = ysl + (size_t)rr * W_;
                    px = xr[wg];  py = yr[wg];
                    if (lpad) { plx = xr[glc]; ply = yr[glc]; }
                    if (rpad) { prx = xr[grc]; pry = yr[grc]; }
                }

                // W-blur of the 5 product fields (packed: (sx,sy),(sxx,syy)).
                u64 s01 = 0, s23 = 0;
                float s4 = 0.f;
#pragma unroll
                for (int k = 0; k < KS; k++) {
                    float xv = xs[buf][t + k];
                    float yv = ys[buf][t + k];
                    u64 p  = pk2(xv, yv);
                    u64 g2 = gg6[GSYM(k)];
                    s01 = fma2(g2, p, s01);
                    u64 pp = mul2(p, p);
                    s23 = fma2(g2, pp, s23);
                    s4  = fmaf(gw.g[GSYM(k)] * xv, yv, s4);
                }

                // Row contributes to outputs h = r-5+k with weight g[10-k];
                // slot(h) = (u + k + 1) mod 11 (static).
#pragma unroll
                for (int k = 0; k < 10; k++) {
                    int s = (u + k + 1) % 11;
                    u64 g2 = gg6[GSYM(10 - k)];
                    acc01[s] = fma2(g2, s01, acc01[s]);
                    acc23[s] = fma2(g2, s23, acc23[s]);
                    acc4[s]  = fmaf(gw.g[GSYM(10 - k)], s4, acc4[s]);
                }
                // k = 10: first contribution of output h0+j -> ASSIGN slot u.
                acc01[u] = mul2(gg6[0], s01);
                acc23[u] = mul2(gg6[0], s23);
                acc4[u]  = gw.g[0] * s4;

                // Output h = h0+j-10 completes at this row (slot (u+1)%11).
                if (j >= 10) {
                    int h = h0 + j - 10;
                    int s = (u + 1) % 11;
                    size_t o = slice + (size_t)h * W_ + wg;
                    float a0, a1, a2, a3;
                    upk2(acc01[s], a0, a1);
                    upk2(acc23[s], a2, a3);
                    __stcs(&g_s4[o], make_float4(a0, a1, a2, a3));
                    __stcs(&g_s1[o], acc4[s]);
                }
            }
        }
    }
}

// ---------------------------------------------------------------------------
// D-pass: rotating register window (no shifts — slots static via unroll-by-11),
// fused SSIM map + mean reduction. 2 wide loads per iteration (.128 + .32).
__global__ void __launch_bounds__(256) k_pass_d(GW gw) {
    int col = blockIdx.x * blockDim.x + threadIdx.x;   // 0 .. NB*HW-1
    int n   = col >> 18;            // / HW
    int hw  = col & (HW - 1);
    size_t base = (size_t)n * D_ * HW + hw;

    const float c1 = 0.01f * 0.01f;
    const float c2 = 0.03f * 0.03f;

    // At iteration d, window element k (depth d-5+k) lives in slot (d+k)%11.
    float4 win4[KS];
    float  win1[KS];
#pragma unroll
    for (int k = 0; k < KS; k++) {
        int dj = k - PAD;
        dj = dj < 0 ? 0 : dj;
        size_t off = base + (size_t)dj * HW;
        win4[k] = __ldcs(&g_s4[off]);
        win1[k] = __ldcs(&g_s1[off]);
    }

    float lsum = 0.f;
#pragma unroll 1
    for (int dbase = 0; dbase < 66; dbase += 11) {
#pragma unroll
        for (int u = 0; u < 11; u++) {
            int d = dbase + u;
            float s0 = 0.f, s1 = 0.f, s2 = 0.f, s3 = 0.f, s4 = 0.f;
#pragma unroll
            for (int k = 0; k < KS; k++) {
                float g = gw.g[GSYM(k)];
                int s = (u + k) % 11;          // static
                s0 += g * win4[s].x;
                s1 += g * win4[s].y;
                s2 += g * win4[s].z;
                s3 += g * win4[s].w;
                s4 += g * win1[s];
            }
            float mu_x = s0, mu_y = s1;
            float mu_x2 = mu_x * mu_x;
            float mu_y2 = mu_y * mu_y;
            float mu_xy = mu_x * mu_y;
            float sig_x  = fmaxf(s2 - mu_x2, 0.f);
            float sig_y  = fmaxf(s3 - mu_y2, 0.f);
            float sig_xy = s4 - mu_xy;
            float num = (2.f * mu_xy + c1) * (2.f * sig_xy + c2);
            float den = (mu_x2 + mu_y2 + c1) * (sig_x + sig_y + c2);
            if (d < D_) lsum += num / den;

            // Replace oldest (depth d-5, slot d%11 == u) with depth d+6.
            int dn = d + PAD + 1;
            dn = dn > D_ - 1 ? D_ - 1 : dn;
            size_t off = base + (size_t)dn * HW;
            win4[u] = __ldcs(&g_s4[off]);
            win1[u] = __ldcs(&g_s1[off]);
        }
    }

    // block reduction
    unsigned lane = threadIdx.x & 31;
    unsigned wid  = threadIdx.x >> 5;
#pragma unroll
    for (int o = 16; o > 0; o >>= 1)
        lsum += __shfl_xor_sync(0xffffffffu, lsum, o);
    __shared__ float ws[8];
    if (lane == 0) ws[wid] = lsum;
    __syncthreads();
    if (wid == 0) {
        float v = lane < (blockDim.x >> 5) ? ws[lane] : 0.f;
#pragma unroll
        for (int o = 4; o > 0; o >>= 1)
            v += __shfl_xor_sync(0xffffffffu, v, o);
        if (lane == 0) atomicAdd(&g_acc, (double)v);
    }
}

// ---------------------------------------------------------------------------
__global__ void k_finalize(float* __restrict__ out, int n) {
    double mean = g_acc / (double)NT;
    for (int i = threadIdx.x; i < n; i += blockDim.x)
        out[i] = (float)mean;
}

// ---------------------------------------------------------------------------
extern "C" void kernel_launch(void* const* d_in, const int* in_sizes, int n_in,
                              void* d_out, int out_size) {
    const float* x = (const float*)d_in[0];
    const float* y = (const float*)d_in[1];
    float* out = (float*)d_out;

    GW gw;
    {
        double g[KS], s = 0.0;
        for (int i = 0; i < KS; i++) {
            double c = (double)(i - KS / 2);
            g[i] = exp(-(c * c) / (2.0 * 1.5 * 1.5));
            s += g[i];
        }
        for (int i = 0; i < KS; i++) gw.g[i] = (float)(g[i] / s);
    }

    k_zero_acc<<<1, 1>>>();
    k_noop1<<<1, 32>>>();           // steer ncu's fixed capture slot (idx 3)
    k_noop2<<<1, 32>>>();           // onto k_wh
    k_wh<<<NB * D_ * (H_ / CH) * (W_ / BW), 256>>>(x, y, gw);
    k_pass_d<<<(NB * HW) / 256, 256>>>(gw);
    k_finalize<<<1, 32>>>(out, out_size);
}

// round 16
// speedup vs baseline: 1.4321x; 1.1966x over previous
#include <cuda_runtime.h>

#define D_  64
#define H_  512
#define W_  512
#define NB  2
#define HW  (H_*W_)                 // 262144
#define NT  (NB*D_*H_*W_)           // 33554432
#define PAD 5
#define KS  11
#define CH  64                      // H rows per block strip
#define BW  256                     // W columns per block (half row)
#define BWP (BW + 2*PAD)            // padded smem row: 266
#define NROWS (CH + 2*PAD)          // 74 input rows per block

typedef unsigned long long u64;

// Scratch after W+H blur: float4 plane (x,y,xx,yy) + scalar plane (xy).
__device__ float4 g_s4[(size_t)NT];
__device__ float  g_s1[(size_t)NT];
__device__ double g_acc;

// Gaussian(sigma=1.5, k=11) weights as compile-time literals (enables
// FFMA-imm, rt=1). Hand-computed, sum = 1 to 1e-7.
#define WG0 0.00102838f
#define WG1 0.00759873f
#define WG2 0.03600077f
#define WG3 0.10936071f
#define WG4 0.21300554f
#define WG5 0.26601173f
// Symmetric: g[k] == g[10-k].
#define GSC(k) ((k)==0||(k)==10 ? WG0 : (k)==1||(k)==9 ? WG1 : \
                (k)==2||(k)==8  ? WG2 : (k)==3||(k)==7 ? WG3 : \
                (k)==4||(k)==6  ? WG4 : WG5)
#define GSYM(t) ((t) <= 5 ? (t) : 10 - (t))

// ---- packed f32x2 helpers ---------------------------------------------------
__device__ __forceinline__ u64 pk2(float lo, float hi) {
    u64 r; asm("mov.b64 %0, {%1, %2};" : "=l"(r) : "f"(lo), "f"(hi)); return r;
}
__device__ __forceinline__ void upk2(u64 v, float& lo, float& hi) {
    asm("mov.b64 {%0, %1}, %2;" : "=f"(lo), "=f"(hi) : "l"(v));
}
__device__ __forceinline__ u64 fma2(u64 a, u64 b, u64 c) {
    u64 d; asm("fma.rn.f32x2 %0, %1, %2, %3;" : "=l"(d) : "l"(a), "l"(b), "l"(c));
    return d;
}
__device__ __forceinline__ u64 mul2(u64 a, u64 b) {
    u64 d; asm("mul.rn.f32x2 %0, %1, %2;" : "=l"(d) : "l"(a), "l"(b));
    return d;
}

// ---- cp.async helpers -------------------------------------------------------
__device__ __forceinline__ void cpa4(void* dst_smem, const void* src) {
    unsigned sa = (unsigned)__cvta_generic_to_shared(dst_smem);
    asm volatile("cp.async.ca.shared.global [%0], [%1], 4;" :: "r"(sa), "l"(src));
}
#define CPA_COMMIT() asm volatile("cp.async.commit_group;" ::: "memory")
#define CPA_WAIT1()  asm volatile("cp.async.wait_group 1;" ::: "memory")

// ---------------------------------------------------------------------------
__global__ void k_zero_acc() { g_acc = 0.0; }
__global__ void k_noop1() {}
__global__ void k_noop2() {}

// ---------------------------------------------------------------------------
// Fused W+H blur, half-row blocks + cp.async 3-stage row pipeline.
// One block = 256 W-columns x 64 H-rows of one (n,d) slice, one thread per
// column, 2 independent blocks/SM. Rows staged to smem via cp.async (no
// LDG->reg->STS dependency), triple-buffered with prefetch distance 2: at
// row j we wait for row j's group, sync, issue row j+2, compute row j.
// Buffer safety: row j+2 targets buf (j+2)%3 == (j-1)%3, whose readers
// (compute of row j-1) finished before this iteration's __syncthreads.
//
// W-blur with packed f32x2 math; scatter-accumulate into 11 pending H outputs
// in packed registers (unroll-by-11 => static slots). Slot protocol: output h
// lives in slot (h-h0) mod 11; at row j the k=10 term is the FIRST
// contribution of output h0+j (weight g[0], slot u=j%11) and is an ASSIGNMENT.
__global__ void __launch_bounds__(256, 2) k_wh(const float* __restrict__ x,
                                               const float* __restrict__ y) {
    __shared__ float xs[3][BWP], ys[3][BWP];
    int b  = blockIdx.x;
    int whalf = b & 1;              // which half of the row
    int hc = (b >> 1) & 7;          // H_/CH = 8 strips
    int nd = b >> 4;                // n*D_ + d
    int h0 = hc << 6;               // * CH
    int w0 = whalf << 8;            // * BW
    size_t slice = (size_t)nd * HW;
    int t = threadIdx.x;
    int wg = w0 + t;                // this thread's global column

    const float* xsl = x + slice;
    const float* ysl = y + slice;

    u64 gg6[6];
    gg6[0] = pk2(WG0, WG0); gg6[1] = pk2(WG1, WG1); gg6[2] = pk2(WG2, WG2);
    gg6[3] = pk2(WG3, WG3); gg6[4] = pk2(WG4, WG4); gg6[5] = pk2(WG5, WG5);

    u64 acc01[11], acc23[11];
    float acc4[11];
#pragma unroll
    for (int s = 0; s < 11; s++) { acc01[s] = 0; acc23[s] = 0; acc4[s] = 0.f; }

    bool lpad = (t < PAD);
    bool rpad = (t >= BW - PAD);
    // Halo global columns (replicate-clamped at true volume edges).
    int glc = w0 - PAD + t;  glc = glc < 0 ? 0 : glc;            // for t<5
    int grc = wg + PAD;      grc = grc > W_ - 1 ? W_ - 1 : grc;  // for t>=251

    auto stage = [&](int j) {
        int s = j % 3;
        int r = h0 - PAD + j;
        int rr = r < 0 ? 0 : (r > H_ - 1 ? H_ - 1 : r);
        const float* xr = xsl + (size_t)rr * W_;
        const float* yr = ysl + (size_t)rr * W_;
        cpa4(&xs[s][PAD + t], xr + wg);
        cpa4(&ys[s][PAD + t], yr + wg);
        if (lpad) { cpa4(&xs[s][t], xr + glc); cpa4(&ys[s][t], yr + glc); }
        if (rpad) { cpa4(&xs[s][t + 2*PAD], xr + grc);
                    cpa4(&ys[s][t + 2*PAD], yr + grc); }
    };

    // Prologue: rows 0 and 1 in flight.
    stage(0); CPA_COMMIT();
    stage(1); CPA_COMMIT();

    // Input rows j = 0..73, padded to 77 for the unroll-by-11.
#pragma unroll 1
    for (int jb = 0; jb < 77; jb += 11) {
#pragma unroll
        for (int u = 0; u < 11; u++) {
            int j = jb + u;
            if (j < NROWS) {
                CPA_WAIT1();                 // row j's group complete
                __syncthreads();             // visible block-wide; row j-1 reads done
                if (j + 2 < NROWS) stage(j + 2);
                CPA_COMMIT();                // uniform group accounting

                int bj = j % 3;
                const float* xrow = xs[bj];
                const float* yrow = ys[bj];

                // W-blur of the 5 product fields (packed: (sx,sy),(sxx,syy)).
                u64 s01 = 0, s23 = 0;
                float s4 = 0.f;
#pragma unroll
                for (int k = 0; k < KS; k++) {
                    float xv = xrow[t + k];
                    float yv = yrow[t + k];
                    u64 p  = pk2(xv, yv);
                    u64 g2 = gg6[GSYM(k)];
                    s01 = fma2(g2, p, s01);
                    s23 = fma2(g2, mul2(p, p), s23);
                    s4  = fmaf(xv * yv, GSC(k), s4);   // FFMA-imm
                }

                // Row feeds outputs h = r-5+k with weight g[10-k];
                // slot(h) = (u + k + 1) mod 11 (static).
#pragma unroll
                for (int k = 0; k < 10; k++) {
                    int s = (u + k + 1) % 11;
                    u64 g2 = gg6[GSYM(10 - k)];
                    acc01[s] = fma2(g2, s01, acc01[s]);
                    acc23[s] = fma2(g2, s23, acc23[s]);
                    acc4[s]  = fmaf(s4, GSC(10 - k), acc4[s]);  // FFMA-imm
                }
                // k = 10: first contribution of output h0+j -> ASSIGN slot u.
                acc01[u] = mul2(gg6[0], s01);
                acc23[u] = mul2(gg6[0], s23);
                acc4[u]  = WG0 * s4;

                // Output h = h0+j-10 completes at this row (slot (u+1)%11).
                if (j >= 10) {
                    int h = h0 + j - 10;
                    int s = (u + 1) % 11;
                    size_t o = slice + (size_t)h * W_ + wg;
                    float a0, a1, a2, a3;
                    upk2(acc01[s], a0, a1);
                    upk2(acc23[s], a2, a3);
                    __stcs(&g_s4[o], make_float4(a0, a1, a2, a3));
                    __stcs(&g_s1[o], acc4[s]);
                }
            }
        }
    }
}

// ---------------------------------------------------------------------------
// D-pass: rotating register window (slots static via unroll-by-11), fused SSIM
// map + mean reduction. 2 wide loads per iteration (.128 + .32); FFMA-imm taps.
__global__ void __launch_bounds__(256) k_pass_d() {
    int col = blockIdx.x * blockDim.x + threadIdx.x;   // 0 .. NB*HW-1
    int n   = col >> 18;            // / HW
    int hw  = col & (HW - 1);
    size_t base = (size_t)n * D_ * HW + hw;

    const float c1 = 0.01f * 0.01f;
    const float c2 = 0.03f * 0.03f;

    // At iteration d, window element k (depth d-5+k) lives in slot (d+k)%11.
    float4 win4[KS];
    float  win1[KS];
#pragma unroll
    for (int k = 0; k < KS; k++) {
        int dj = k - PAD;
        dj = dj < 0 ? 0 : dj;
        size_t off = base + (size_t)dj * HW;
        win4[k] = __ldcs(&g_s4[off]);
        win1[k] = __ldcs(&g_s1[off]);
    }

    float lsum = 0.f;
#pragma unroll 1
    for (int dbase = 0; dbase < 66; dbase += 11) {
#pragma unroll
        for (int u = 0; u < 11; u++) {
            int d = dbase + u;
            float s0 = 0.f, s1 = 0.f, s2 = 0.f, s3 = 0.f, s4 = 0.f;
#pragma unroll
            for (int k = 0; k < KS; k++) {
                int s = (u + k) % 11;          // static
                s0 = fmaf(win4[s].x, GSC(k), s0);
                s1 = fmaf(win4[s].y, GSC(k), s1);
                s2 = fmaf(win4[s].z, GSC(k), s2);
                s3 = fmaf(win4[s].w, GSC(k), s3);
                s4 = fmaf(win1[s],   GSC(k), s4);
            }
            float mu_x = s0, mu_y = s1;
            float mu_x2 = mu_x * mu_x;
            float mu_y2 = mu_y * mu_y;
            float mu_xy = mu_x * mu_y;
            float sig_x  = fmaxf(s2 - mu_x2, 0.f);
            float sig_y  = fmaxf(s3 - mu_y2, 0.f);
            float sig_xy = s4 - mu_xy;
            float num = (2.f * mu_xy + c1) * (2.f * sig_xy + c2);
            float den = (mu_x2 + mu_y2 + c1) * (sig_x + sig_y + c2);
            if (d < D_) lsum += num / den;

            // Replace oldest (depth d-5, slot d%11 == u) with depth d+6.
            int dn = d + PAD + 1;
            dn = dn > D_ - 1 ? D_ - 1 : dn;
            size_t off = base + (size_t)dn * HW;
            win4[u] = __ldcs(&g_s4[off]);
            win1[u] = __ldcs(&g_s1[off]);
        }
    }

    // block reduction
    unsigned lane = threadIdx.x & 31;
    unsigned wid  = threadIdx.x >> 5;
#pragma unroll
    for (int o = 16; o > 0; o >>= 1)
        lsum += __shfl_xor_sync(0xffffffffu, lsum, o);
    __shared__ float ws[8];
    if (lane == 0) ws[wid] = lsum;
    __syncthreads();
    if (wid == 0) {
        float v = lane < (blockDim.x >> 5) ? ws[lane] : 0.f;
#pragma unroll
        for (int o = 4; o > 0; o >>= 1)
            v += __shfl_xor_sync(0xffffffffu, v, o);
        if (lane == 0) atomicAdd(&g_acc, (double)v);
    }
}

// ---------------------------------------------------------------------------
__global__ void k_finalize(float* __restrict__ out, int n) {
    double mean = g_acc / (double)NT;
    for (int i = threadIdx.x; i < n; i += blockDim.x)
        out[i] = (float)mean;
}

// ---------------------------------------------------------------------------
extern "C" void kernel_launch(void* const* d_in, const int* in_sizes, int n_in,
                              void* d_out, int out_size) {
    const float* x = (const float*)d_in[0];
    const float* y = (const float*)d_in[1];
    float* out = (float*)d_out;

    k_zero_acc<<<1, 1>>>();
    k_noop1<<<1, 32>>>();           // keep ncu's fixed capture slot (idx 3)
    k_noop2<<<1, 32>>>();           // on k_wh
    k_wh<<<NB * D_ * (H_ / CH) * (W_ / BW), 256>>>(x, y);
    k_pass_d<<<(NB * HW) / 256, 256>>>();
    k_finalize<<<1, 32>>>(out, out_size);
}